// round 10
// baseline (speedup 1.0000x reference)
#include <cuda_runtime.h>
#include <math.h>

// Problem shape (fixed): x [8, 128, 512, 512] f32, conv_w [16,1,3,3], conv_b [16]
// out [8, 1, 512, 512] f32 with per-tile reassembly layout:
//   out_flat = b*HW + seg*16384 + r*128 + c, seg = ti*4 + tj
#define Bb   8
#define Cc   128
#define Hh   512
#define Ww   512
#define HW   (Hh * Ww)        /* 262144 */
#define CHW  (Cc * HW)
#define TS   128              /* tile side */
#define NSEG 16

// One 3x3-row conv accumulation pass (dr = kernel row) for a float4 group.
__device__ __forceinline__ void conv_acc(const float* __restrict__ sr, int cq,
                                         const float* __restrict__ wt, int dr,
                                         float& a0, float& a1, float& a2, float& a3) {
    float4 vc = *reinterpret_cast<const float4*>(sr + cq);
    float vm1 = (cq == 0)   ? 0.f : sr[cq - 1];
    float vp4 = (cq == 124) ? 0.f : sr[cq + 4];
    float w0 = wt[dr * 3], w1 = wt[dr * 3 + 1], w2 = wt[dr * 3 + 2];
    a0 = fmaf(w0, vm1,  fmaf(w1, vc.x, fmaf(w2, vc.y, a0)));
    a1 = fmaf(w0, vc.x, fmaf(w1, vc.y, fmaf(w2, vc.z, a1)));
    a2 = fmaf(w0, vc.y, fmaf(w1, vc.z, fmaf(w2, vc.w, a2)));
    a3 = fmaf(w0, vc.z, fmaf(w1, vc.w, fmaf(w2, vp4,  a3)));
}

__device__ __forceinline__ void sig_store(float a0, float a1, float a2, float a3,
                                          float bias, float* __restrict__ outp) {
    float4 o;
    o.x = 1.f / (1.f + __expf(-(a0 + bias)));
    o.y = 1.f / (1.f + __expf(-(a1 + bias)));
    o.z = 1.f / (1.f + __expf(-(a2 + bias)));
    o.w = 1.f / (1.f + __expf(-(a3 + bias)));
    *reinterpret_cast<float4*>(outp) = o;
}

// Fused + software-pipelined over a pair of adjacent 8-row strips.
// 10 warps: warp w owns smem row w (one 128-col row; lane = float4 group ->
// 512B contiguous per warp per channel, perfectly balanced).
// Phase 1: l2 rows for strip A (8 + 2 halo) -> sA, sync.
// Phase 2: strip B channel loop split into 4 groups of 32 channels; between
//          groups, threads 0..255 run one conv-A slice (3 row passes + final
//          sigmoid/store) -> conv A issues in the shadow of B's load stalls.
// Phase 3: sqrt/sts B, sync, conv B (exposed tail, ~half the old bubble).
__global__ void __launch_bounds__(320, 5) fused_kernel(const float* __restrict__ x,
                                                       const float* __restrict__ conv_w,
                                                       const float* __restrict__ conv_b,
                                                       float* __restrict__ out) {
    __shared__ float sA[10][128];
    __shared__ float sB[10][128];

    int p    = blockIdx.x;            // strip-pair index
    int q    = p & 7;                 // pair within tile (8 pairs of 16 rows)
    int tile = p >> 3;
    int seg  = tile & 15;
    int b    = tile >> 4;
    int ti   = seg >> 2;
    int tj   = seg & 3;
    int r0A  = q * 16;                // strip A first output row
    int r0B  = r0A + 8;               // strip B first output row
    int tid  = threadIdx.x;
    int w    = tid >> 5;              // warp 0..9 = smem row
    int l    = tid & 31;              // lane = float4 column group

    const float* xbase = x + (size_t)b * CHW + (size_t)(ti * TS) * Ww + tj * TS;

    // ---- Phase 1: strip A l2 rows ----
    {
        int gr = r0A - 1 + w;         // -1 .. r0A+8
        float ax = 0.f, ay = 0.f, az = 0.f, aw = 0.f;
        if ((unsigned)gr < (unsigned)TS) {
            const float4* xp = reinterpret_cast<const float4*>(
                xbase + (size_t)gr * Ww) + l;
            #pragma unroll 8
            for (int c = 0; c < Cc; ++c) {
                float4 v = __ldg(xp + (size_t)c * (HW / 4));
                ax = fmaf(v.x, v.x, ax);
                ay = fmaf(v.y, v.y, ay);
                az = fmaf(v.z, v.z, az);
                aw = fmaf(v.w, v.w, aw);
            }
        }
        float4 r;
        r.x = sqrtf(ax); r.y = sqrtf(ay); r.z = sqrtf(az); r.w = sqrtf(aw);
        *reinterpret_cast<float4*>(&sA[w][l * 4]) = r;
    }

    // Weights + bias (uniform per block; persist in regs for both strips)
    float wt[9];
    const float* wseg = conv_w + seg * 9;
    #pragma unroll
    for (int k = 0; k < 9; ++k) wt[k] = __ldg(wseg + k);
    float bias = __ldg(conv_b + seg);

    __syncthreads();

    // conv coordinates (threads 0..255 = warps 0..7, warp-uniform predicate)
    int orow = tid >> 5;
    int cq   = (tid & 31) * 4;
    float a0 = 0.f, a1 = 0.f, a2 = 0.f, a3 = 0.f;

    // ---- Phase 2: strip B loads (4 groups of 32 ch) interleaved with conv A ----
    {
        int gr = r0B - 1 + w;         // r0A+7 .. r0B+8; OOB only for (w==9 && q==7)
        bool act = (unsigned)gr < (unsigned)TS;
        const float4* xp = reinterpret_cast<const float4*>(
            xbase + (size_t)(act ? gr : 0) * Ww) + l;
        float bx = 0.f, by = 0.f, bz = 0.f, bw2 = 0.f;

        #pragma unroll
        for (int g = 0; g < 4; ++g) {
            if (act) {
                #pragma unroll 8
                for (int c = g * 32; c < g * 32 + 32; ++c) {
                    float4 v = __ldg(xp + (size_t)c * (HW / 4));
                    bx  = fmaf(v.x, v.x, bx);
                    by  = fmaf(v.y, v.y, by);
                    bz  = fmaf(v.z, v.z, bz);
                    bw2 = fmaf(v.w, v.w, bw2);
                }
            }
            if (tid < 256) {
                if (g < 3) {
                    conv_acc(sA[orow + g], cq, wt, g, a0, a1, a2, a3);
                } else {
                    size_t oofs = (size_t)b * HW + (size_t)seg * (TS * TS)
                                + (size_t)(r0A + orow) * TS + cq;
                    sig_store(a0, a1, a2, a3, bias, out + oofs);
                }
            }
        }

        float4 r;
        r.x = sqrtf(bx); r.y = sqrtf(by); r.z = sqrtf(bz); r.w = sqrtf(bw2);
        *reinterpret_cast<float4*>(&sB[w][l * 4]) = r;
    }

    __syncthreads();

    // ---- Phase 3: conv B (exposed tail) ----
    if (tid < 256) {
        a0 = a1 = a2 = a3 = 0.f;
        #pragma unroll
        for (int dr = 0; dr < 3; ++dr)
            conv_acc(sB[orow + dr], cq, wt, dr, a0, a1, a2, a3);
        size_t oofs = (size_t)b * HW + (size_t)seg * (TS * TS)
                    + (size_t)(r0B + orow) * TS + cq;
        sig_store(a0, a1, a2, a3, bias, out + oofs);
    }
}

extern "C" void kernel_launch(void* const* d_in, const int* in_sizes, int n_in,
                              void* d_out, int out_size) {
    const float* x  = (const float*)d_in[0];
    const float* cw = (const float*)d_in[1];
    const float* cb = (const float*)d_in[2];
    float* out = (float*)d_out;

    // 8 strip-pairs x 16 segs x 8 batches = 1024 blocks, 320 threads each
    fused_kernel<<<Bb * NSEG * 8, 320>>>(x, cw, cb, out);
}

// round 11
// speedup vs baseline: 1.3952x; 1.3952x over previous
#include <cuda_runtime.h>
#include <math.h>

// Problem shape (fixed): x [8, 128, 512, 512] f32, conv_w [16,1,3,3], conv_b [16]
// out [8, 1, 512, 512] f32 with per-tile reassembly layout:
//   out_flat = b*HW + seg*16384 + r*128 + c, seg = ti*4 + tj
#define Bb   8
#define Cc   128
#define Hh   512
#define Ww   512
#define HW   (Hh * Ww)        /* 262144 */
#define CHW  (Cc * HW)
#define TS   128              /* tile side */
#define NSEG 16

// Fully fused kernel (R3 geometry — the best measured configuration).
// One block = one 16-row x 128-col strip of one (batch, segment) tile.
// Phase 1: l2 = sqrt(sum_c x^2) for 18 rows (16 + 2 halo) into SMEM.
//          18 warps, one warp per row (perfect balance), lane = float4
//          column group -> 512B contiguous per warp per channel; the
//          128-channel loop is a single uninterrupted max-MLP stream.
// Phase 2: per-tile 3x3 conv (zero pad at tile edges) + bias + sigmoid,
//          float4 streaming stores (__stwt: no reuse, keep L2 for halo).
__global__ void __launch_bounds__(576) fused_kernel(const float* __restrict__ x,
                                                    const float* __restrict__ conv_w,
                                                    const float* __restrict__ conv_b,
                                                    float* __restrict__ out) {
    __shared__ float s[18][128];

    int bid   = blockIdx.x;
    int strip = bid & 7;          // 8 strips of 16 rows per tile
    int seg   = (bid >> 3) & 15;
    int b     = bid >> 7;
    int ti    = seg >> 2;
    int tj    = seg & 3;
    int r0    = strip * 16;
    int tid   = threadIdx.x;

    int row = tid >> 5;           // smem row 0..17 (warp-uniform)
    int cf  = tid & 31;           // float4 column group 0..31
    int gr  = r0 - 1 + row;       // row within tile (-1 .. 128)

    // ---- Phase 1: channel-L2 into smem ----
    float ax = 0.f, ay = 0.f, az = 0.f, aw = 0.f;
    if ((unsigned)gr < (unsigned)TS) {
        const float4* xp = reinterpret_cast<const float4*>(
            x + (size_t)b * CHW + (size_t)(ti * TS + gr) * Ww + tj * TS) + cf;
        #pragma unroll 8
        for (int c = 0; c < Cc; ++c) {
            float4 v = __ldg(xp + (size_t)c * (HW / 4));
            ax = fmaf(v.x, v.x, ax);
            ay = fmaf(v.y, v.y, ay);
            az = fmaf(v.z, v.z, az);
            aw = fmaf(v.w, v.w, aw);
        }
    }
    float4 r;
    r.x = sqrtf(ax);
    r.y = sqrtf(ay);
    r.z = sqrtf(az);
    r.w = sqrtf(aw);
    *reinterpret_cast<float4*>(&s[row][cf * 4]) = r;   // zeros for out-of-tile halo rows

    // Weights + bias into registers (uniform per block)
    float w[9];
    const float* wseg = conv_w + seg * 9;
    #pragma unroll
    for (int k = 0; k < 9; ++k) w[k] = __ldg(wseg + k);
    float bias = __ldg(conv_b + seg);

    __syncthreads();

    // ---- Phase 2: conv + sigmoid, 512 float4 output groups, threads 0..511 ----
    if (tid < 512) {
        int orow = tid >> 5;          // output row within strip; smem rows orow..orow+2
        int cq   = (tid & 31) * 4;    // output col of first element

        float a0 = 0.f, a1 = 0.f, a2 = 0.f, a3 = 0.f;
        #pragma unroll
        for (int dr = 0; dr < 3; ++dr) {
            const float* sr = s[orow + dr];
            float4 vc = *reinterpret_cast<const float4*>(&sr[cq]);
            float vm1 = (cq == 0)   ? 0.f : sr[cq - 1];
            float vp4 = (cq == 124) ? 0.f : sr[cq + 4];
            float w0 = w[dr * 3], w1 = w[dr * 3 + 1], w2 = w[dr * 3 + 2];
            a0 = fmaf(w0, vm1,  fmaf(w1, vc.x, fmaf(w2, vc.y, a0)));
            a1 = fmaf(w0, vc.x, fmaf(w1, vc.y, fmaf(w2, vc.z, a1)));
            a2 = fmaf(w0, vc.y, fmaf(w1, vc.z, fmaf(w2, vc.w, a2)));
            a3 = fmaf(w0, vc.z, fmaf(w1, vc.w, fmaf(w2, vp4,  a3)));
        }

        float4 o;
        o.x = 1.f / (1.f + __expf(-(a0 + bias)));
        o.y = 1.f / (1.f + __expf(-(a1 + bias)));
        o.z = 1.f / (1.f + __expf(-(a2 + bias)));
        o.w = 1.f / (1.f + __expf(-(a3 + bias)));

        size_t oofs = (size_t)b * HW + (size_t)seg * (TS * TS)
                    + (size_t)(r0 + orow) * TS + cq;
        __stwt(reinterpret_cast<float4*>(out + oofs), o);   // streaming store
    }
}

extern "C" void kernel_launch(void* const* d_in, const int* in_sizes, int n_in,
                              void* d_out, int out_size) {
    const float* x  = (const float*)d_in[0];
    const float* cw = (const float*)d_in[1];
    const float* cb = (const float*)d_in[2];
    float* out = (float*)d_out;

    // 8 strips x 16 segs x 8 batches = 1024 blocks, 576 threads each
    fused_kernel<<<Bb * NSEG * 8, 576>>>(x, cw, cb, out);
}

// round 12
// speedup vs baseline: 1.4045x; 1.0066x over previous
#include <cuda_runtime.h>
#include <math.h>
#include <stdint.h>

// Problem shape (fixed): x [8, 128, 512, 512] f32, conv_w [16,1,3,3], conv_b [16]
// out [8, 1, 512, 512] f32 with per-tile reassembly layout:
//   out_flat = b*HW + seg*16384 + r*128 + c, seg = ti*4 + tj
#define Bb   8
#define Cc   128
#define Hh   512
#define Ww   512
#define HW   (Hh * Ww)        /* 262144 */
#define CHW  (Cc * HW)
#define TS   128              /* tile side */
#define NSEG 16

__device__ __forceinline__ uint32_t smem_u32(const void* p) {
    return (uint32_t)__cvta_generic_to_shared(p);
}

__device__ __forceinline__ void mbar_init(uint32_t a, int cnt) {
    asm volatile("mbarrier.init.shared.b64 [%0], %1;" :: "r"(a), "r"(cnt) : "memory");
}

__device__ __forceinline__ void mbar_arrive(uint32_t a) {
    // release.cta semantics: orders the preceding STS before waiters' acquire
    asm volatile("mbarrier.arrive.release.cta.shared::cta.b64 _, [%0];" :: "r"(a) : "memory");
}

__device__ __forceinline__ void mbar_wait_p0(uint32_t a) {
    uint32_t done = 0;
    while (!done) {
        asm volatile(
            "{\n\t.reg .pred p;\n\t"
            "mbarrier.try_wait.parity.acquire.cta.shared::cta.b64 p, [%1], 0;\n\t"
            "selp.b32 %0, 1, 0, p;\n\t}"
            : "=r"(done) : "r"(a) : "memory");
    }
}

// Fully fused kernel, R3 geometry + per-row mbarrier dataflow (no block barrier
// between load and conv phases).
// One block = one 16-row x 128-col strip of one (batch, segment) tile.
// 18 warps: warp w computes l2 row w (16 + 2 halo; lane = float4 col group,
// single uninterrupted 128-channel max-MLP load stream), STS, then arrives on
// mbar[w]. Conv warp w (w<16) waits only on mbar[w..w+2] and convolves row w
// (lane = one float4 output group) -> early rows' conv overlaps late rows'
// loads; the block-wide drain disappears.
__global__ void __launch_bounds__(576) fused_kernel(const float* __restrict__ x,
                                                    const float* __restrict__ conv_w,
                                                    const float* __restrict__ conv_b,
                                                    float* __restrict__ out) {
    __shared__ float s[18][128];
    __shared__ __align__(8) unsigned long long mbar[18];

    int bid   = blockIdx.x;
    int strip = bid & 7;          // 8 strips of 16 rows per tile
    int seg   = (bid >> 3) & 15;
    int b     = bid >> 7;
    int ti    = seg >> 2;
    int tj    = seg & 3;
    int r0    = strip * 16;
    int tid   = threadIdx.x;

    int row = tid >> 5;           // warp 0..17 = smem row (warp-uniform)
    int l   = tid & 31;           // lane = float4 column group
    int gr  = r0 - 1 + row;       // row within tile (-1 .. 128)

    // ---- mbarrier init (one per row), then make visible block-wide ----
    if (tid < 18) mbar_init(smem_u32(&mbar[tid]), 1);
    __syncthreads();

    // ---- Phase 1: channel-L2 into smem (uninterrupted load stream) ----
    float ax = 0.f, ay = 0.f, az = 0.f, aw = 0.f;
    if ((unsigned)gr < (unsigned)TS) {
        const float4* xp = reinterpret_cast<const float4*>(
            x + (size_t)b * CHW + (size_t)(ti * TS + gr) * Ww + tj * TS) + l;
        #pragma unroll 8
        for (int c = 0; c < Cc; ++c) {
            float4 v = __ldg(xp + (size_t)c * (HW / 4));
            ax = fmaf(v.x, v.x, ax);
            ay = fmaf(v.y, v.y, ay);
            az = fmaf(v.z, v.z, az);
            aw = fmaf(v.w, v.w, aw);
        }
    }
    float4 r;
    r.x = sqrtf(ax);
    r.y = sqrtf(ay);
    r.z = sqrtf(az);
    r.w = sqrtf(aw);
    *reinterpret_cast<float4*>(&s[row][l * 4]) = r;    // zeros for out-of-tile halo rows
    __syncwarp();
    if (l == 0) mbar_arrive(smem_u32(&mbar[row]));     // row ready

    // ---- Phase 2: conv + sigmoid; warp w handles output row w (w < 16) ----
    if (row < 16) {
        // Weights + bias (independent of row readiness; issues during waits)
        float wt[9];
        const float* wseg = conv_w + seg * 9;
        #pragma unroll
        for (int k = 0; k < 9; ++k) wt[k] = __ldg(wseg + k);
        float bias = __ldg(conv_b + seg);

        // Wait only for the 3 rows this warp consumes
        mbar_wait_p0(smem_u32(&mbar[row]));
        mbar_wait_p0(smem_u32(&mbar[row + 1]));
        mbar_wait_p0(smem_u32(&mbar[row + 2]));

        int cq = l * 4;           // output col of first element

        float a0 = 0.f, a1 = 0.f, a2 = 0.f, a3 = 0.f;
        #pragma unroll
        for (int dr = 0; dr < 3; ++dr) {
            const float* sr = s[row + dr];
            float4 vc = *reinterpret_cast<const float4*>(&sr[cq]);
            float vm1 = (cq == 0)   ? 0.f : sr[cq - 1];
            float vp4 = (cq == 124) ? 0.f : sr[cq + 4];
            float w0 = wt[dr * 3], w1 = wt[dr * 3 + 1], w2 = wt[dr * 3 + 2];
            a0 = fmaf(w0, vm1,  fmaf(w1, vc.x, fmaf(w2, vc.y, a0)));
            a1 = fmaf(w0, vc.x, fmaf(w1, vc.y, fmaf(w2, vc.z, a1)));
            a2 = fmaf(w0, vc.y, fmaf(w1, vc.z, fmaf(w2, vc.w, a2)));
            a3 = fmaf(w0, vc.z, fmaf(w1, vc.w, fmaf(w2, vp4,  a3)));
        }

        float4 o;
        o.x = 1.f / (1.f + __expf(-(a0 + bias)));
        o.y = 1.f / (1.f + __expf(-(a1 + bias)));
        o.z = 1.f / (1.f + __expf(-(a2 + bias)));
        o.w = 1.f / (1.f + __expf(-(a3 + bias)));

        size_t oofs = (size_t)b * HW + (size_t)seg * (TS * TS)
                    + (size_t)(r0 + row) * TS + cq;
        *reinterpret_cast<float4*>(out + oofs) = o;
    }
}

extern "C" void kernel_launch(void* const* d_in, const int* in_sizes, int n_in,
                              void* d_out, int out_size) {
    const float* x  = (const float*)d_in[0];
    const float* cw = (const float*)d_in[1];
    const float* cb = (const float*)d_in[2];
    float* out = (float*)d_out;

    // 8 strips x 16 segs x 8 batches = 1024 blocks, 576 threads each
    fused_kernel<<<Bb * NSEG * 8, 576>>>(x, cw, cb, out);
}

// round 13
// speedup vs baseline: 1.4116x; 1.0051x over previous
#include <cuda_runtime.h>
#include <math.h>
#include <stdint.h>

// Problem shape (fixed): x [8, 128, 512, 512] f32, conv_w [16,1,3,3], conv_b [16]
// out [8, 1, 512, 512] f32 with per-tile reassembly layout:
//   out_flat = b*HW + seg*16384 + r*128 + c, seg = ti*4 + tj
#define Bb   8
#define Cc   128
#define Hh   512
#define Ww   512
#define HW   (Hh * Ww)        /* 262144 */
#define CHW  (Cc * HW)
#define TS   128              /* tile side */
#define NSEG 16

__device__ __forceinline__ uint32_t smem_u32(const void* p) {
    return (uint32_t)__cvta_generic_to_shared(p);
}

__device__ __forceinline__ void mbar_init(uint32_t a, int cnt) {
    asm volatile("mbarrier.init.shared.b64 [%0], %1;" :: "r"(a), "r"(cnt) : "memory");
}

__device__ __forceinline__ void mbar_arrive(uint32_t a) {
    // release.cta: orders the preceding STS before waiters' acquire
    asm volatile("mbarrier.arrive.release.cta.shared::cta.b64 _, [%0];" :: "r"(a) : "memory");
}

__device__ __forceinline__ void mbar_wait_p0(uint32_t a) {
    uint32_t done = 0;
    while (!done) {
        asm volatile(
            "{\n\t.reg .pred p;\n\t"
            "mbarrier.try_wait.parity.acquire.cta.shared::cta.b64 p, [%1], 0;\n\t"
            "selp.b32 %0, 1, 0, p;\n\t}"
            : "=r"(done) : "r"(a) : "memory");
    }
}

// Fully fused kernel: R3 strip geometry + per-row mbarrier dataflow (no block
// barrier between load and conv) + streaming output stores.
// One block = one 16-row x 128-col strip of one (batch, segment) tile.
// 18 warps: warp w computes the channel-L2 of smem row w (16 rows + 2 halo;
// lane = float4 col group -> 512B contiguous per warp per channel; single
// uninterrupted 128-channel load stream), STS, arrive mbar[w]. Conv warp w
// (w<16) waits only on mbar[w..w+2], then 3x3 conv (zero pad at tile edges)
// + bias + sigmoid, one float4 output group per lane, __stwt store.
__global__ void __launch_bounds__(576) fused_kernel(const float* __restrict__ x,
                                                    const float* __restrict__ conv_w,
                                                    const float* __restrict__ conv_b,
                                                    float* __restrict__ out) {
    __shared__ float s[18][128];
    __shared__ __align__(8) unsigned long long mbar[18];

    int bid   = blockIdx.x;
    int strip = bid & 7;          // 8 strips of 16 rows per tile
    int seg   = (bid >> 3) & 15;
    int b     = bid >> 7;
    int ti    = seg >> 2;
    int tj    = seg & 3;
    int r0    = strip * 16;
    int tid   = threadIdx.x;

    int row = tid >> 5;           // warp 0..17 = smem row (warp-uniform)
    int l   = tid & 31;           // lane = float4 column group
    int gr  = r0 - 1 + row;       // row within tile (-1 .. 128)

    // ---- mbarrier init (one per row), then make visible block-wide ----
    if (tid < 18) mbar_init(smem_u32(&mbar[tid]), 1);
    __syncthreads();

    // ---- Phase 1: channel-L2 into smem (uninterrupted load stream) ----
    float ax = 0.f, ay = 0.f, az = 0.f, aw = 0.f;
    if ((unsigned)gr < (unsigned)TS) {
        const float4* xp = reinterpret_cast<const float4*>(
            x + (size_t)b * CHW + (size_t)(ti * TS + gr) * Ww + tj * TS) + l;
        #pragma unroll 16
        for (int c = 0; c < Cc; ++c) {
            float4 v = __ldg(xp + (size_t)c * (HW / 4));
            ax = fmaf(v.x, v.x, ax);
            ay = fmaf(v.y, v.y, ay);
            az = fmaf(v.z, v.z, az);
            aw = fmaf(v.w, v.w, aw);
        }
    }
    float4 r;
    r.x = sqrtf(ax);
    r.y = sqrtf(ay);
    r.z = sqrtf(az);
    r.w = sqrtf(aw);
    *reinterpret_cast<float4*>(&s[row][l * 4]) = r;    // zeros for out-of-tile halo rows
    __syncwarp();
    if (l == 0) mbar_arrive(smem_u32(&mbar[row]));     // row ready

    // ---- Phase 2: conv + sigmoid; warp w handles output row w (w < 16) ----
    if (row < 16) {
        // Weights + bias (independent of row readiness; issues during waits)
        float wt[9];
        const float* wseg = conv_w + seg * 9;
        #pragma unroll
        for (int k = 0; k < 9; ++k) wt[k] = __ldg(wseg + k);
        float bias = __ldg(conv_b + seg);

        // Wait only for the 3 rows this warp consumes
        mbar_wait_p0(smem_u32(&mbar[row]));
        mbar_wait_p0(smem_u32(&mbar[row + 1]));
        mbar_wait_p0(smem_u32(&mbar[row + 2]));

        int cq = l * 4;           // output col of first element

        float a0 = 0.f, a1 = 0.f, a2 = 0.f, a3 = 0.f;
        #pragma unroll
        for (int dr = 0; dr < 3; ++dr) {
            const float* sr = s[row + dr];
            float4 vc = *reinterpret_cast<const float4*>(&sr[cq]);
            float vm1 = (cq == 0)   ? 0.f : sr[cq - 1];
            float vp4 = (cq == 124) ? 0.f : sr[cq + 4];
            float w0 = wt[dr * 3], w1 = wt[dr * 3 + 1], w2 = wt[dr * 3 + 2];
            a0 = fmaf(w0, vm1,  fmaf(w1, vc.x, fmaf(w2, vc.y, a0)));
            a1 = fmaf(w0, vc.x, fmaf(w1, vc.y, fmaf(w2, vc.z, a1)));
            a2 = fmaf(w0, vc.y, fmaf(w1, vc.z, fmaf(w2, vc.w, a2)));
            a3 = fmaf(w0, vc.z, fmaf(w1, vc.w, fmaf(w2, vp4,  a3)));
        }

        float4 o;
        o.x = 1.f / (1.f + __expf(-(a0 + bias)));
        o.y = 1.f / (1.f + __expf(-(a1 + bias)));
        o.z = 1.f / (1.f + __expf(-(a2 + bias)));
        o.w = 1.f / (1.f + __expf(-(a3 + bias)));

        size_t oofs = (size_t)b * HW + (size_t)seg * (TS * TS)
                    + (size_t)(r0 + row) * TS + cq;
        __stwt(reinterpret_cast<float4*>(out + oofs), o);   // streaming store
    }
}

extern "C" void kernel_launch(void* const* d_in, const int* in_sizes, int n_in,
                              void* d_out, int out_size) {
    const float* x  = (const float*)d_in[0];
    const float* cw = (const float*)d_in[1];
    const float* cb = (const float*)d_in[2];
    float* out = (float*)d_out;

    // 8 strips x 16 segs x 8 batches = 1024 blocks, 576 threads each
    fused_kernel<<<Bb * NSEG * 8, 576>>>(x, cw, cb, out);
}